// round 1
// baseline (speedup 1.0000x reference)
#include <cuda_runtime.h>

// ContinousActionDecoder: out[q] = action_set[argmax_n (a_n . p_q / ||a_n||)]
// (per-query norm ||p_q|| > 0 is a monotonic per-query scale -> dropped)
//
// N = 1e6 action rows, D = 64, Q = 128 queries (32*4).
// Strategy: fp32x2 packed FMA (Blackwell f32x2 pipe) dot products, queries
// staged in smem, row held in registers, argmax via packed (key|~idx)
// atomicMax in smem then merged to a __device__ global, then a gather kernel.

#define D 64
#define QMAX 128

__device__ unsigned long long g_best[QMAX];

// map float -> monotonically ordered uint
__device__ __forceinline__ unsigned int fkey(float f) {
    unsigned int u = __float_as_uint(f);
    return (u & 0x80000000u) ? ~u : (u | 0x80000000u);
}

__device__ __forceinline__ unsigned long long fma2(unsigned long long a,
                                                   unsigned long long b,
                                                   unsigned long long c) {
    unsigned long long d;
    asm("fma.rn.f32x2 %0, %1, %2, %3;" : "=l"(d) : "l"(a), "l"(b), "l"(c));
    return d;
}

__device__ __forceinline__ void unpack2(unsigned long long v, float& lo, float& hi) {
    asm("mov.b64 {%0, %1}, %2;" : "=f"(lo), "=f"(hi) : "l"(v));
}

__global__ void init_best() {
    if (threadIdx.x < QMAX) g_best[threadIdx.x] = 0ull;
}

__global__ void __launch_bounds__(256, 2)
sim_argmax(const float* __restrict__ actions, const float* __restrict__ pred,
           int N, int Q)
{
    // queries as f32x2 pairs: layout sq[q * 32 + c], c = dim-pair index
    __shared__ unsigned long long sq[QMAX * (D / 2)];
    __shared__ unsigned long long sbest[QMAX];

    const int tid = threadIdx.x;
    const unsigned long long* predq =
        reinterpret_cast<const unsigned long long*>(pred);
    for (int k = tid; k < Q * (D / 2); k += blockDim.x) sq[k] = predq[k];
    for (int k = tid; k < QMAX; k += blockDim.x) sbest[k] = 0ull;
    __syncthreads();

    const long long stride = (long long)gridDim.x * blockDim.x;
    for (long long r = (long long)blockIdx.x * blockDim.x + tid; r < N;
         r += stride) {
        // load this thread's row: 16 x LDG.128 (full-line utilization,
        // adjacent 16B chunks hit the same sectors -> L1 absorbs overfetch)
        const ulonglong2* row2 =
            reinterpret_cast<const ulonglong2*>(actions + r * D);
        ulonglong2 rr[D / 4];
#pragma unroll
        for (int c = 0; c < D / 4; ++c) rr[c] = row2[c];

        // row norm via packed FMA
        unsigned long long ss2 = 0ull;
#pragma unroll
        for (int c = 0; c < D / 4; ++c) {
            ss2 = fma2(rr[c].x, rr[c].x, ss2);
            ss2 = fma2(rr[c].y, rr[c].y, ss2);
        }
        float s0, s1;
        unpack2(ss2, s0, s1);
        float ss = s0 + s1;
        float inv = (ss > 1e-30f) ? rsqrtf(ss) : 0.0f;

        // 8 queries at a time: 8 f32x2 accumulators, row in regs,
        // query pairs via LDS.128 broadcast (2 FMA2 per LDS.128)
        for (int qb = 0; qb < Q; qb += 8) {
            const ulonglong2* qs2 =
                reinterpret_cast<const ulonglong2*>(&sq[qb * (D / 2)]);
            unsigned long long acc[8] = {0ull, 0ull, 0ull, 0ull,
                                         0ull, 0ull, 0ull, 0ull};
#pragma unroll
            for (int cc = 0; cc < D / 4; ++cc) {
                const unsigned long long rlo = rr[cc].x;
                const unsigned long long rhi = rr[cc].y;
#pragma unroll
                for (int j = 0; j < 8; ++j) {
                    ulonglong2 qv = qs2[j * (D / 4) + cc];
                    acc[j] = fma2(rlo, qv.x, acc[j]);
                    acc[j] = fma2(rhi, qv.y, acc[j]);
                }
            }
#pragma unroll
            for (int j = 0; j < 8; ++j) {
                float lo, hi;
                unpack2(acc[j], lo, hi);
                float score = (lo + hi) * inv;
                int q = qb + j;
                unsigned int k = fkey(score);
                // monotonic filter: stale reads are always <= current,
                // so a skip is always safe; atomic resolves races.
                unsigned long long cur =
                    *(volatile unsigned long long*)&sbest[q];
                if (k >= (unsigned int)(cur >> 32)) {
                    unsigned long long packed =
                        ((unsigned long long)k << 32) |
                        (unsigned long long)(~(unsigned int)r);
                    atomicMax(&sbest[q], packed);
                }
            }
        }
    }

    __syncthreads();
    for (int k = tid; k < Q; k += blockDim.x) {
        unsigned long long v = sbest[k];
        if (v) atomicMax(&g_best[k], v);
    }
}

__global__ void gather(const float* __restrict__ actions,
                       float* __restrict__ out, int Q) {
    int q = blockIdx.x;
    int t = threadIdx.x;
    if (q < Q) {
        unsigned int idx = ~(unsigned int)(g_best[q] & 0xFFFFFFFFull);
        out[(size_t)q * D + t] = actions[(size_t)idx * D + t];
    }
}

extern "C" void kernel_launch(void* const* d_in, const int* in_sizes, int n_in,
                              void* d_out, int out_size) {
    // identify inputs by size: pred_action is the small one
    int ip = 0, ia = 1;
    if (n_in >= 2 && in_sizes[0] > in_sizes[1]) { ip = 1; ia = 0; }
    const float* pred    = (const float*)d_in[ip];
    const float* actions = (const float*)d_in[ia];
    int Q = in_sizes[ip] / D;
    if (Q > QMAX) Q = QMAX;
    int N = in_sizes[ia] / D;

    init_best<<<1, 128>>>();
    sim_argmax<<<304, 256>>>(actions, pred, N, Q);
    gather<<<Q, D>>>(actions, (float*)d_out, Q);
}

// round 2
// speedup vs baseline: 1.3580x; 1.3580x over previous
#include <cuda_runtime.h>
#include <cstdint>

// ContinousActionDecoder: out[q] = action_set[argmax_n (a_n . p_q / ||a_n||)]
// (query norm is a positive per-query scale -> cannot change the argmax)
//
// Register-tiled GEMM: block tile = 128 rows x 128 queries, thread tile =
// 8 rows x 8 queries (4 f32x2 accumulators along Q). Persistent blocks,
// per-thread argmax in registers, cp.async double-buffered A tiles.

#define D     64
#define QMAX  128
#define BM    128
#define TPB   256

__device__ unsigned long long g_best[QMAX];

__device__ __forceinline__ unsigned int fkey(float f) {
    unsigned int u = __float_as_uint(f);
    return (u & 0x80000000u) ? ~u : (u | 0x80000000u);
}

__device__ __forceinline__ unsigned long long fma2(unsigned long long a,
                                                   unsigned long long b,
                                                   unsigned long long c) {
    unsigned long long d;
    asm("fma.rn.f32x2 %0, %1, %2, %3;" : "=l"(d) : "l"(a), "l"(b), "l"(c));
    return d;
}

__device__ __forceinline__ unsigned long long dup2(float a) {
    unsigned long long d;
    asm("mov.b64 %0, {%1, %1};" : "=l"(d) : "f"(a));
    return d;
}

__device__ __forceinline__ void unpack2(unsigned long long v, float& lo, float& hi) {
    asm("mov.b64 {%0, %1}, %2;" : "=f"(lo), "=f"(hi) : "l"(v));
}

__device__ __forceinline__ uint32_t smem_u32(const void* p) {
    uint32_t a;
    asm("{ .reg .u64 t; cvta.to.shared.u64 t, %1; cvt.u32.u64 %0, t; }"
        : "=r"(a) : "l"(p));
    return a;
}

__device__ __forceinline__ void cpa16(uint32_t s, const void* g) {
    asm volatile("cp.async.cg.shared.global [%0], [%1], 16;" :: "r"(s), "l"(g));
}

__global__ void init_best() {
    if (threadIdx.x < QMAX) g_best[threadIdx.x] = 0ull;
}

// smem layout (dynamic):
//   A[2][BM*D] floats         : 65536 B
//   P[D][QMAX/2] u64 (f32x2)  : 32768 B
//   inv[BM] float             :   512 B
//   sbest[QMAX] u64           :  1024 B
#define SMEM_A_BYTES   (2 * BM * D * 4)
#define SMEM_P_BYTES   (D * (QMAX / 2) * 8)
#define SMEM_TOTAL     (SMEM_A_BYTES + SMEM_P_BYTES + BM * 4 + QMAX * 8)

extern "C" __global__ void __launch_bounds__(TPB)
sim_argmax(const float* __restrict__ actions, const float* __restrict__ pred,
           int N, int Q)
{
    extern __shared__ char smem[];
    float* A_s = (float*)smem;                                   // [2][BM*D]
    unsigned long long* P = (unsigned long long*)(smem + SMEM_A_BYTES);
    float* inv_s = (float*)(smem + SMEM_A_BYTES + SMEM_P_BYTES);
    unsigned long long* sbest = (unsigned long long*)(inv_s + BM);

    const int tid = threadIdx.x;
    const int tx  = tid & 15;    // query group: queries tx*8 .. tx*8+7
    const int ty  = tid >> 4;    // row group:   rows    ty*8 .. ty*8+7
    const int m0  = ty * 8;

    // Build P_s[k][qpair] = (pred[2qp][k], pred[2qp+1][k]); zero-pad past Q.
    for (int idx = tid; idx < D * (QMAX / 2); idx += TPB) {
        int k  = idx >> 6;   // / (QMAX/2)
        int qp = idx & 63;
        float lo = 0.f, hi = 0.f;
        if (2 * qp     < Q) lo = pred[(2 * qp)     * D + k];
        if (2 * qp + 1 < Q) hi = pred[(2 * qp + 1) * D + k];
        unsigned long long v;
        asm("mov.b64 %0, {%1, %2};" : "=l"(v) : "f"(lo), "f"(hi));
        P[idx] = v;
    }
    for (int k = tid; k < QMAX; k += TPB) sbest[k] = 0ull;

    // Per-thread running argmax for this thread's 8 queries (fixed forever).
    float        bscore[8];
    unsigned int brow[8];
#pragma unroll
    for (int j = 0; j < 8; ++j) { bscore[j] = -3.4e38f; brow[j] = 0u; }

    const int ntiles = (N + BM - 1) / BM;
    const float4* g4 = (const float4*)actions;

    // prologue: async-load first tile into buffer 0
    long long t0 = blockIdx.x;
    if (t0 < ntiles) {
        long long base = t0 * BM;
        uint32_t dst = smem_u32(A_s);
#pragma unroll
        for (int i = 0; i < 8; ++i) {
            int idx = tid + i * TPB;                 // 0..2047 float4 slots
            long long row = base + (idx >> 4);
            if (row >= N) row = 0;                   // clamp (data unused)
            cpa16(dst + idx * 16, g4 + row * 16 + (idx & 15));
        }
        asm volatile("cp.async.commit_group;");
    }

    int buf = 0;
    for (long long t = t0; t < ntiles; t += gridDim.x, buf ^= 1) {
        asm volatile("cp.async.wait_group 0;");
        __syncthreads();

        // kick next tile load into the other buffer
        long long tn = t + gridDim.x;
        if (tn < ntiles) {
            long long base = tn * BM;
            uint32_t dst = smem_u32(A_s + (buf ^ 1) * BM * D);
#pragma unroll
            for (int i = 0; i < 8; ++i) {
                int idx = tid + i * TPB;
                long long row = base + (idx >> 4);
                if (row >= N) row = 0;
                cpa16(dst + idx * 16, g4 + row * 16 + (idx & 15));
            }
            asm volatile("cp.async.commit_group;");
        }

        const float* Ac = A_s + buf * BM * D;

        // row inverse norms (threads 0..127, skewed k to dodge bank conflicts)
        if (tid < BM) {
            float ss = 0.f;
#pragma unroll
            for (int k = 0; k < D; ++k) {
                int kk = (k + 2 * tid) & (D - 1);
                float a = Ac[tid * D + kk];
                ss = fmaf(a, a, ss);
            }
            inv_s[tid] = (ss > 1e-30f) ? rsqrtf(ss) : 0.f;
        }
        __syncthreads();

        // main GEMM tile: acc[i][p] = f32x2 over query pair (tx*4+p)
        unsigned long long acc[8][4];
#pragma unroll
        for (int i = 0; i < 8; ++i)
#pragma unroll
            for (int p = 0; p < 4; ++p) acc[i][p] = 0ull;

#pragma unroll 4
        for (int k = 0; k < D; ++k) {
            const ulonglong2* qrow =
                (const ulonglong2*)&P[k * (QMAX / 2) + tx * 4];
            ulonglong2 q01 = qrow[0];
            ulonglong2 q23 = qrow[1];
#pragma unroll
            for (int i = 0; i < 8; ++i) {
                unsigned long long dv = dup2(Ac[(m0 + i) * D + k]);
                acc[i][0] = fma2(dv, q01.x, acc[i][0]);
                acc[i][1] = fma2(dv, q01.y, acc[i][1]);
                acc[i][2] = fma2(dv, q23.x, acc[i][2]);
                acc[i][3] = fma2(dv, q23.y, acc[i][3]);
            }
        }

        // epilogue: scale by row inv-norm, update register bests
        long long rb = t * BM + m0;
#pragma unroll
        for (int i = 0; i < 8; ++i) {
            long long r = rb + i;
            if (r < N) {
                float im = inv_s[m0 + i];
#pragma unroll
                for (int p = 0; p < 4; ++p) {
                    float lo, hi;
                    unpack2(acc[i][p], lo, hi);
                    lo *= im; hi *= im;
                    int j0 = 2 * p, j1 = 2 * p + 1;
                    if (lo > bscore[j0]) { bscore[j0] = lo; brow[j0] = (unsigned)r; }
                    if (hi > bscore[j1]) { bscore[j1] = hi; brow[j1] = (unsigned)r; }
                }
            }
        }
    }

    // merge: registers -> block smem -> global
    __syncthreads();
#pragma unroll
    for (int j = 0; j < 8; ++j) {
        int q = tx * 8 + j;
        unsigned long long packed =
            ((unsigned long long)fkey(bscore[j]) << 32) |
            (unsigned long long)(~brow[j]);
        atomicMax(&sbest[q], packed);
    }
    __syncthreads();
    if (tid < QMAX) {
        unsigned long long v = sbest[tid];
        if (v) atomicMax(&g_best[tid], v);
    }
}

__global__ void gather(const float* __restrict__ actions,
                       float* __restrict__ out, int Q) {
    int q = blockIdx.x;
    int t = threadIdx.x;
    if (q < Q) {
        unsigned int idx = ~(unsigned int)(g_best[q] & 0xFFFFFFFFull);
        out[(size_t)q * D + t] = actions[(size_t)idx * D + t];
    }
}

extern "C" void kernel_launch(void* const* d_in, const int* in_sizes, int n_in,
                              void* d_out, int out_size) {
    int ip = 0, ia = 1;
    if (n_in >= 2 && in_sizes[0] > in_sizes[1]) { ip = 1; ia = 0; }
    const float* pred    = (const float*)d_in[ip];
    const float* actions = (const float*)d_in[ia];
    int Q = in_sizes[ip] / D;
    if (Q > QMAX) Q = QMAX;
    int N = in_sizes[ia] / D;

    cudaFuncSetAttribute(sim_argmax,
                         cudaFuncAttributeMaxDynamicSharedMemorySize,
                         SMEM_TOTAL);

    init_best<<<1, 128>>>();
    sim_argmax<<<296, TPB, SMEM_TOTAL>>>(actions, pred, N, Q);
    gather<<<Q, D>>>(actions, (float*)d_out, Q);
}

// round 4
// speedup vs baseline: 1.6937x; 1.2472x over previous
#include <cuda_runtime.h>
#include <cstdint>

// ContinousActionDecoder via classic mma.sync (tf32, m16n8k8), 3-product
// 2-term tf32 split => fp32-grade accuracy. Persistent CTAs, cp.async
// double-buffered fp32 staging, per-thread register argmax.

#define KD      64
#define QMAX    128
#define BM      128
#define TPB     256
#define RSTRIDE 68                     // padded floats per row (16B-aligned, conflict-free)

#define STAGE_BYTES (BM * RSTRIDE * 4)           // 34816
#define OFF_STAGE 0
#define OFF_AH    (2 * STAGE_BYTES)              // 69632
#define OFF_AL    (OFF_AH + STAGE_BYTES)         // 104448
#define OFF_B     (OFF_AL + STAGE_BYTES)         // 139264
#define B_BYTES   (8 * 16 * 32 * 16)             // 65536
#define OFF_INV   (OFF_B + B_BYTES)              // 204800
#define OFF_SBEST (OFF_INV + 512)                // 205312
#define SMEM_TOTAL (OFF_SBEST + 1024)            // 206336

__device__ unsigned long long g_best[QMAX];

__device__ __forceinline__ unsigned int fkey(float f) {
    unsigned int u = __float_as_uint(f);
    return (u & 0x80000000u) ? ~u : (u | 0x80000000u);
}
__device__ __forceinline__ uint32_t smem_u32(const void* p) {
    uint32_t a;
    asm("{ .reg .u64 t; cvta.to.shared.u64 t, %1; cvt.u32.u64 %0, t; }"
        : "=r"(a) : "l"(p));
    return a;
}
__device__ __forceinline__ void cpa16(uint32_t s, const void* g) {
    asm volatile("cp.async.cg.shared.global [%0], [%1], 16;" :: "r"(s), "l"(g));
}
__device__ __forceinline__ void split_tf32(float x, uint32_t& h, uint32_t& l) {
    asm("cvt.rna.tf32.f32 %0, %1;" : "=r"(h) : "f"(x));
    float r = x - __uint_as_float(h);
    asm("cvt.rna.tf32.f32 %0, %1;" : "=r"(l) : "f"(r));
}
#define MMA_TF32(d, a0,a1,a2,a3, b0,b1) \
    asm volatile("mma.sync.aligned.m16n8k8.row.col.f32.tf32.tf32.f32 " \
        "{%0,%1,%2,%3}, {%4,%5,%6,%7}, {%8,%9}, {%0,%1,%2,%3};" \
        : "+f"((d)[0]), "+f"((d)[1]), "+f"((d)[2]), "+f"((d)[3]) \
        : "r"(a0), "r"(a1), "r"(a2), "r"(a3), "r"(b0), "r"(b1))

__global__ void init_best() {
    if (threadIdx.x < QMAX) g_best[threadIdx.x] = 0ull;
}

__device__ __forceinline__ void load_tile_async(uint32_t stage_s,
                                                const float4* g4,
                                                long long tile, int N, int tid)
{
#pragma unroll
    for (int i = 0; i < 8; ++i) {
        int j   = tid + i * TPB;           // 0..2047 16B chunks
        int row = j >> 4, k4 = j & 15;
        long long gr = tile * BM + row;
        if (gr >= N) gr = N - 1;
        cpa16(stage_s + (uint32_t)(row * RSTRIDE + k4 * 4) * 4u,
              g4 + gr * (KD / 4) + k4);
    }
    asm volatile("cp.async.commit_group;" ::: "memory");
}

extern "C" __global__ void __launch_bounds__(TPB, 1)
sim_argmax(const float* __restrict__ actions, const float* __restrict__ pred,
           int N, int Q)
{
    extern __shared__ char smem[];
    const uint32_t sb = smem_u32(smem);
    float*    stage = (float*)smem;
    uint32_t* ahs   = (uint32_t*)(smem + OFF_AH);
    uint32_t* als   = (uint32_t*)(smem + OFF_AL);
    float*    inv_s = (float*)(smem + OFF_INV);
    unsigned long long* sbest = (unsigned long long*)(smem + OFF_SBEST);

    const int tid  = threadIdx.x;
    const int lane = tid & 31;
    const int w    = tid >> 5;

    // ---- build B fragments once (fragment-ordered: [s][nt][lane] = uint4
    //      {bh0, bh1, bl0, bl1}), queries zero-padded to 128
    for (int i = 0; i < 16; ++i) {
        int slot = tid + i * TPB;                 // 0..4095
        int s  = slot >> 9;
        int nt = (slot >> 5) & 15;
        int l  = slot & 31;
        int q  = nt * 8 + (l >> 2);
        int k0 = s * 8 + (l & 3);
        float x0 = 0.f, x1 = 0.f;
        if (q < Q) {
            x0 = pred[q * KD + k0];
            x1 = pred[q * KD + k0 + 4];
        }
        uint32_t h0, l0, h1, l1;
        split_tf32(x0, h0, l0);
        split_tf32(x1, h1, l1);
        uint4 v; v.x = h0; v.y = h1; v.z = l0; v.w = l1;
        *(uint4*)(smem + OFF_B + slot * 16) = v;
    }
    if (tid < QMAX) sbest[tid] = 0ull;

    // per-thread running argmax over 32 fixed query slots
    float        bs[32];
    unsigned int br[32];
#pragma unroll
    for (int j = 0; j < 32; ++j) { bs[j] = -3.4e38f; br[j] = 0u; }

    const long long ntiles = ((long long)N + BM - 1) / BM;
    const float4* g4 = (const float4*)actions;

    long long tile = blockIdx.x;
    if (tile < ntiles) load_tile_async(sb + OFF_STAGE, g4, tile, N, tid);

    int ib = 0;
    for (; tile < ntiles; tile += gridDim.x, ib ^= 1) {
        asm volatile("cp.async.wait_group 0;" ::: "memory");
        __syncthreads();

        // ---- convert staged fp32 -> tf32 hi/lo tiles + exact fp32 norms
        {
            const float* st = stage + ib * (BM * RSTRIDE);
            int r = tid >> 1, h = tid & 1;
            int base = r * RSTRIDE + h * 32;
            float ss = 0.f;
#pragma unroll
            for (int i = 0; i < 8; ++i) {
                float4 x = *(const float4*)&st[base + i * 4];
                uint4 hh, ll;
                split_tf32(x.x, hh.x, ll.x);
                split_tf32(x.y, hh.y, ll.y);
                split_tf32(x.z, hh.z, ll.z);
                split_tf32(x.w, hh.w, ll.w);
                *(uint4*)&ahs[base + i * 4] = hh;
                *(uint4*)&als[base + i * 4] = ll;
                ss = fmaf(x.x, x.x, ss);
                ss = fmaf(x.y, x.y, ss);
                ss = fmaf(x.z, x.z, ss);
                ss = fmaf(x.w, x.w, ss);
            }
            ss += __shfl_xor_sync(0xffffffffu, ss, 1);
            if (h == 0) inv_s[r] = (ss > 1e-30f) ? rsqrtf(ss) : 0.f;
        }
        __syncthreads();

        // ---- kick next tile's cp.async (overlaps with MMA below)
        long long tn = tile + gridDim.x;
        if (tn < ntiles)
            load_tile_async(sb + OFF_STAGE + (ib ^ 1) * STAGE_BYTES,
                            g4, tn, N, tid);

        // ---- warp-level MMA: warp w owns rows [w*16, w*16+16), all 128 q
        const int r0 = w * 16 + (lane >> 2);
        const int c0 = lane & 3;
        const long long gr0 = tile * BM + r0;
        const float im0 = inv_s[r0];
        const float im1 = inv_s[r0 + 8];
        const bool ok0 = (gr0 < N);
        const bool ok1 = (gr0 + 8 < N);

#pragma unroll
        for (int hf = 0; hf < 2; ++hf) {
            float d[8][4];
#pragma unroll
            for (int n = 0; n < 8; ++n)
#pragma unroll
                for (int c = 0; c < 4; ++c) d[n][c] = 0.f;

#pragma unroll
            for (int s = 0; s < 8; ++s) {
                const int ka = s * 8 + c0;
                uint32_t a0 = ahs[r0 * RSTRIDE + ka];
                uint32_t a1 = ahs[(r0 + 8) * RSTRIDE + ka];
                uint32_t a2 = ahs[r0 * RSTRIDE + ka + 4];
                uint32_t a3 = ahs[(r0 + 8) * RSTRIDE + ka + 4];
                uint32_t e0 = als[r0 * RSTRIDE + ka];
                uint32_t e1 = als[(r0 + 8) * RSTRIDE + ka];
                uint32_t e2 = als[r0 * RSTRIDE + ka + 4];
                uint32_t e3 = als[(r0 + 8) * RSTRIDE + ka + 4];
#pragma unroll
                for (int n = 0; n < 8; ++n) {
                    int nt = hf * 8 + n;
                    uint4 b = *(const uint4*)(smem + OFF_B +
                              (((s * 16 + nt) * 32 + lane) << 4));
                    MMA_TF32(d[n], a0, a1, a2, a3, b.x, b.y);  // Ah*Bh
                    MMA_TF32(d[n], a0, a1, a2, a3, b.z, b.w);  // Ah*Bl
                    MMA_TF32(d[n], e0, e1, e2, e3, b.x, b.y);  // Al*Bh
                }
            }
            // epilogue: scale by row inv-norm, update register argmax
#pragma unroll
            for (int n = 0; n < 8; ++n) {
                int nt = hf * 8 + n;
                int j = nt * 2;
                float s0 = d[n][0] * im0, s1 = d[n][1] * im0;
                float s2 = d[n][2] * im1, s3 = d[n][3] * im1;
                if (ok0) {
                    if (s0 > bs[j])     { bs[j] = s0;     br[j] = (unsigned)gr0; }
                    if (s1 > bs[j + 1]) { bs[j + 1] = s1; br[j + 1] = (unsigned)gr0; }
                }
                if (ok1) {
                    if (s2 > bs[j])     { bs[j] = s2;     br[j] = (unsigned)(gr0 + 8); }
                    if (s3 > bs[j + 1]) { bs[j + 1] = s3; br[j + 1] = (unsigned)(gr0 + 8); }
                }
            }
        }
    }

    // ---- merge: shuffle-reduce lanes sharing the same query, then atomics
    __syncthreads();
#pragma unroll
    for (int j = 0; j < 32; ++j) {
        unsigned long long pk = 0ull;
        if (bs[j] > -1e37f)
            pk = ((unsigned long long)fkey(bs[j]) << 32) |
                 (unsigned long long)(~br[j]);
#pragma unroll
        for (int off = 4; off <= 16; off <<= 1) {
            unsigned long long o = __shfl_xor_sync(0xffffffffu, pk, off);
            if (o > pk) pk = o;
        }
        if ((lane & 28) == 0 && pk) {
            int nt = j >> 1;
            int q = nt * 8 + (lane & 3) * 2 + (j & 1);
            atomicMax(&sbest[q], pk);
        }
    }
    __syncthreads();
    if (tid < QMAX) {
        unsigned long long v = sbest[tid];
        if (v) atomicMax(&g_best[tid], v);
    }
}

__global__ void gather(const float* __restrict__ actions,
                       float* __restrict__ out, int Q) {
    int q = blockIdx.x;
    int t = threadIdx.x;
    if (q < Q) {
        unsigned int idx = ~(unsigned int)(g_best[q] & 0xFFFFFFFFull);
        out[(size_t)q * KD + t] = actions[(size_t)idx * KD + t];
    }
}

extern "C" void kernel_launch(void* const* d_in, const int* in_sizes, int n_in,
                              void* d_out, int out_size) {
    int ip = 0, ia = 1;
    if (n_in >= 2 && in_sizes[0] > in_sizes[1]) { ip = 1; ia = 0; }
    const float* pred    = (const float*)d_in[ip];
    const float* actions = (const float*)d_in[ia];
    int Q = in_sizes[ip] / KD;
    if (Q > QMAX) Q = QMAX;
    int N = in_sizes[ia] / KD;

    cudaFuncSetAttribute(sim_argmax,
                         cudaFuncAttributeMaxDynamicSharedMemorySize,
                         SMEM_TOTAL);

    init_best<<<1, 128>>>();
    sim_argmax<<<148, TPB, SMEM_TOTAL>>>(actions, pred, N, Q);
    gather<<<Q, KD>>>(actions, (float*)d_out, Q);
}

// round 5
// speedup vs baseline: 2.3366x; 1.3796x over previous
#include <cuda_runtime.h>
#include <cstdint>

// ContinousActionDecoder via mma.sync m16n8k16.bf16 with exact 4-product
// 2-term bf16 split (hh+hl+lh+ll => cos error ~2e-6). Rows pre-scaled by
// inv-norm before split. Persistent CTAs, cp.async double-buffered staging,
// per-thread register argmax.

#define KD      64
#define QMAX    128
#define BM      128
#define TPB     256
#define RSTRIDE 68                      // staged fp32 floats per row
#define ARS     36                      // bf16-pair u32s per row (32 + pad 4)

#define STAGE_BYTES (BM * RSTRIDE * 4)           // 34816
#define OFF_STAGE 0
#define OFF_AH    (2 * STAGE_BYTES)              // 69632
#define OFF_AL    (OFF_AH + BM * ARS * 4)        // 88064
#define OFF_B     (106496)                       // OFF_AL + 18432
#define B_BYTES   (4 * 16 * 32 * 16)             // 32768
#define OFF_SBEST (OFF_B + B_BYTES)              // 139264
#define SMEM_TOTAL (OFF_SBEST + 1024)            // 140288

__device__ unsigned long long g_best[QMAX];

__device__ __forceinline__ unsigned int fkey(float f) {
    unsigned int u = __float_as_uint(f);
    return (u & 0x80000000u) ? ~u : (u | 0x80000000u);
}
__device__ __forceinline__ uint32_t smem_u32(const void* p) {
    uint32_t a;
    asm("{ .reg .u64 t; cvta.to.shared.u64 t, %1; cvt.u32.u64 %0, t; }"
        : "=r"(a) : "l"(p));
    return a;
}
__device__ __forceinline__ void cpa16(uint32_t s, const void* g) {
    asm volatile("cp.async.cg.shared.global [%0], [%1], 16;" :: "r"(s), "l"(g));
}
// pack two f32 -> bf16x2 (x0 -> low half, x1 -> high half)
__device__ __forceinline__ uint32_t bfp(float x1, float x0) {
    uint32_t r;
    asm("cvt.rn.bf16x2.f32 %0, %1, %2;" : "=r"(r) : "f"(x1), "f"(x0));
    return r;
}
// split pair: h = bf16x2(x1,x0), l = bf16x2 of exact residuals
__device__ __forceinline__ void split2(float x0, float x1,
                                       uint32_t& h, uint32_t& l) {
    h = bfp(x1, x0);
    float h0 = __uint_as_float(h << 16);          // exact widen
    float h1 = __uint_as_float(h & 0xffff0000u);
    l = bfp(x1 - h1, x0 - h0);
}
#define MMA_BF16(d, a0,a1,a2,a3, b0,b1) \
    asm volatile("mma.sync.aligned.m16n8k16.row.col.f32.bf16.bf16.f32 " \
        "{%0,%1,%2,%3}, {%4,%5,%6,%7}, {%8,%9}, {%0,%1,%2,%3};" \
        : "+f"((d)[0]), "+f"((d)[1]), "+f"((d)[2]), "+f"((d)[3]) \
        : "r"(a0), "r"(a1), "r"(a2), "r"(a3), "r"(b0), "r"(b1))

__global__ void init_best() {
    if (threadIdx.x < QMAX) g_best[threadIdx.x] = 0ull;
}

__device__ __forceinline__ void load_tile_async(uint32_t stage_s,
                                                const float4* g4,
                                                long long tile, int N, int tid)
{
#pragma unroll
    for (int i = 0; i < 8; ++i) {
        int j   = tid + i * TPB;            // 0..2047 16B chunks
        int row = j >> 4, k4 = j & 15;
        long long gr = tile * BM + row;
        if (gr >= N) gr = N - 1;
        cpa16(stage_s + (uint32_t)(row * RSTRIDE + k4 * 4) * 4u,
              g4 + gr * (KD / 4) + k4);
    }
    asm volatile("cp.async.commit_group;" ::: "memory");
}

extern "C" __global__ void __launch_bounds__(TPB, 1)
sim_argmax(const float* __restrict__ actions, const float* __restrict__ pred,
           int N, int Q)
{
    extern __shared__ char smem[];
    const uint32_t sb = smem_u32(smem);
    float*    stage = (float*)smem;
    uint32_t* ahs   = (uint32_t*)(smem + OFF_AH);
    uint32_t* als   = (uint32_t*)(smem + OFF_AL);
    unsigned long long* sbest = (unsigned long long*)(smem + OFF_SBEST);

    const int tid  = threadIdx.x;
    const int lane = tid & 31;
    const int w    = tid >> 5;

    // ---- build B fragments once: [ks][nt][lane] -> uint4 {bh0,bh1,bl0,bl1}
    //      b0 covers k = ks*16 + (lane&3)*2 {+0,+1}; b1 covers +8.
#pragma unroll
    for (int i = 0; i < 8; ++i) {
        int slot = tid + i * TPB;                 // 0..2047
        int ks = slot >> 9;
        int nt = (slot >> 5) & 15;
        int l  = slot & 31;
        int q  = nt * 8 + (l >> 2);
        int k0 = ks * 16 + (l & 3) * 2;
        float x0 = 0.f, x1 = 0.f, x2 = 0.f, x3 = 0.f;
        if (q < Q) {
            x0 = pred[q * KD + k0];
            x1 = pred[q * KD + k0 + 1];
            x2 = pred[q * KD + k0 + 8];
            x3 = pred[q * KD + k0 + 9];
        }
        uint4 v;
        split2(x0, x1, v.x, v.z);
        split2(x2, x3, v.y, v.w);
        *(uint4*)(smem + OFF_B + slot * 16) = v;
    }
    if (tid < QMAX) sbest[tid] = 0ull;

    // per-thread running argmax over 32 fixed query slots
    float        bs[32];
    unsigned int br[32];
#pragma unroll
    for (int j = 0; j < 32; ++j) { bs[j] = -3.4e38f; br[j] = 0u; }

    const long long ntiles = ((long long)N + BM - 1) / BM;
    const float4* g4 = (const float4*)actions;

    long long tile = blockIdx.x;
    if (tile < ntiles) load_tile_async(sb + OFF_STAGE, g4, tile, N, tid);

    int ib = 0;
    for (; tile < ntiles; tile += gridDim.x, ib ^= 1) {
        asm volatile("cp.async.wait_group 0;" ::: "memory");
        __syncthreads();

        // ---- convert: fp32 row -> inv-norm pre-scaled bf16 hi/lo
        {
            const float* st = stage + ib * (BM * RSTRIDE);
            int r = tid >> 1, h = tid & 1;
            const float* rp = st + r * RSTRIDE + h * 32;
            float4 x[8];
            float ss = 0.f;
#pragma unroll
            for (int i = 0; i < 8; ++i) {
                x[i] = *(const float4*)&rp[i * 4];
                ss = fmaf(x[i].x, x[i].x, ss);
                ss = fmaf(x[i].y, x[i].y, ss);
                ss = fmaf(x[i].z, x[i].z, ss);
                ss = fmaf(x[i].w, x[i].w, ss);
            }
            ss += __shfl_xor_sync(0xffffffffu, ss, 1);
            float inv = (ss > 1e-30f) ? rsqrtf(ss) : 0.f;

            uint32_t hu[16], lu[16];
#pragma unroll
            for (int i = 0; i < 8; ++i) {
                float f0 = x[i].x * inv, f1 = x[i].y * inv;
                float f2 = x[i].z * inv, f3 = x[i].w * inv;
                split2(f0, f1, hu[i * 2],     lu[i * 2]);
                split2(f2, f3, hu[i * 2 + 1], lu[i * 2 + 1]);
            }
            uint32_t* hp = ahs + r * ARS + h * 16;
            uint32_t* lp = als + r * ARS + h * 16;
#pragma unroll
            for (int i = 0; i < 4; ++i) {
                *(uint4*)&hp[i * 4] = *(uint4*)&hu[i * 4];
                *(uint4*)&lp[i * 4] = *(uint4*)&lu[i * 4];
            }
        }
        __syncthreads();

        // ---- kick next tile's cp.async (overlaps MMA below)
        long long tn = tile + gridDim.x;
        if (tn < ntiles)
            load_tile_async(sb + OFF_STAGE + (ib ^ 1) * STAGE_BYTES,
                            g4, tn, N, tid);

        // ---- MMA: warp w owns rows [w*16, w*16+16), all 128 queries
        const int r0 = w * 16 + (lane >> 2);
        const int c4 = lane & 3;
        const long long gr0 = tile * BM + r0;
        const bool ok0 = (gr0 < N);
        const bool ok1 = (gr0 + 8 < N);

#pragma unroll
        for (int hf = 0; hf < 2; ++hf) {
            float d[8][4];
#pragma unroll
            for (int n = 0; n < 8; ++n)
#pragma unroll
                for (int c = 0; c < 4; ++c) d[n][c] = 0.f;

#pragma unroll
            for (int ks = 0; ks < 4; ++ks) {
                const int kb = ks * 8 + c4;
                uint32_t a0 = ahs[r0 * ARS + kb];
                uint32_t a1 = ahs[(r0 + 8) * ARS + kb];
                uint32_t a2 = ahs[r0 * ARS + kb + 4];
                uint32_t a3 = ahs[(r0 + 8) * ARS + kb + 4];
                uint32_t e0 = als[r0 * ARS + kb];
                uint32_t e1 = als[(r0 + 8) * ARS + kb];
                uint32_t e2 = als[r0 * ARS + kb + 4];
                uint32_t e3 = als[(r0 + 8) * ARS + kb + 4];
#pragma unroll
                for (int n = 0; n < 8; ++n) {
                    int nt = hf * 8 + n;
                    uint4 b = *(const uint4*)(smem + OFF_B +
                              (((ks * 16 + nt) * 32 + lane) << 4));
                    MMA_BF16(d[n], a0, a1, a2, a3, b.x, b.y);  // hh
                    MMA_BF16(d[n], a0, a1, a2, a3, b.z, b.w);  // h*l
                    MMA_BF16(d[n], e0, e1, e2, e3, b.x, b.y);  // l*h
                    MMA_BF16(d[n], e0, e1, e2, e3, b.z, b.w);  // l*l
                }
            }
            // epilogue: scores already normalized -> direct argmax update
#pragma unroll
            for (int n = 0; n < 8; ++n) {
                int nt = hf * 8 + n;
                int j = nt * 2;
                if (ok0) {
                    if (d[n][0] > bs[j])     { bs[j] = d[n][0];     br[j] = (unsigned)gr0; }
                    if (d[n][1] > bs[j + 1]) { bs[j + 1] = d[n][1]; br[j + 1] = (unsigned)gr0; }
                }
                if (ok1) {
                    if (d[n][2] > bs[j])     { bs[j] = d[n][2];     br[j] = (unsigned)(gr0 + 8); }
                    if (d[n][3] > bs[j + 1]) { bs[j + 1] = d[n][3]; br[j + 1] = (unsigned)(gr0 + 8); }
                }
            }
        }
    }

    // ---- merge: shuffle-reduce lanes sharing a query, then atomics
    __syncthreads();
#pragma unroll
    for (int j = 0; j < 32; ++j) {
        unsigned long long pk = 0ull;
        if (bs[j] > -1e37f)
            pk = ((unsigned long long)fkey(bs[j]) << 32) |
                 (unsigned long long)(~br[j]);
#pragma unroll
        for (int off = 4; off <= 16; off <<= 1) {
            unsigned long long o = __shfl_xor_sync(0xffffffffu, pk, off);
            if (o > pk) pk = o;
        }
        if ((lane & 28) == 0 && pk) {
            int nt = j >> 1;
            int q = nt * 8 + (lane & 3) * 2 + (j & 1);
            atomicMax(&sbest[q], pk);
        }
    }
    __syncthreads();
    if (tid < QMAX) {
        unsigned long long v = sbest[tid];
        if (v) atomicMax(&g_best[tid], v);
    }
}

__global__ void gather(const float* __restrict__ actions,
                       float* __restrict__ out, int Q) {
    int q = blockIdx.x;
    int t = threadIdx.x;
    if (q < Q) {
        unsigned int idx = ~(unsigned int)(g_best[q] & 0xFFFFFFFFull);
        out[(size_t)q * KD + t] = actions[(size_t)idx * KD + t];
    }
}

extern "C" void kernel_launch(void* const* d_in, const int* in_sizes, int n_in,
                              void* d_out, int out_size) {
    int ip = 0, ia = 1;
    if (n_in >= 2 && in_sizes[0] > in_sizes[1]) { ip = 1; ia = 0; }
    const float* pred    = (const float*)d_in[ip];
    const float* actions = (const float*)d_in[ia];
    int Q = in_sizes[ip] / KD;
    if (Q > QMAX) Q = QMAX;
    int N = in_sizes[ia] / KD;

    cudaFuncSetAttribute(sim_argmax,
                         cudaFuncAttributeMaxDynamicSharedMemorySize,
                         SMEM_TOTAL);

    init_best<<<1, 128>>>();
    sim_argmax<<<148, TPB, SMEM_TOTAL>>>(actions, pred, N, Q);
    gather<<<Q, KD>>>(actions, (float*)d_out, Q);
}

// round 6
// speedup vs baseline: 2.6078x; 1.1161x over previous
#include <cuda_runtime.h>
#include <cuda_fp16.h>
#include <cstdint>

// ContinousActionDecoder: mma.sync m16n8k16.f16, 3-product 2-term fp16 split
// (hh+hl+lh, dropped ll <= 2^-22 rel). Rows pre-scaled by exact fp32 inv-norm.
// Warp-specialized: warps 0-3 consume (MMA+argmax), warps 4-7 produce
// (cp.async stage -> fp16 split frags), double-buffered, 1 barrier/tile.

#define KD      64
#define QMAX    128
#define BM      128
#define TPB     256
#define RSTRIDE 68                       // staged fp32 floats per row
#define ARS     36                       // f16x2 u32s per row (32 + pad)

#define STAGE_BYTES (BM * RSTRIDE * 4)   // 34816
#define FRAG_BYTES  (BM * ARS * 4)       // 18432 (one of ah/al)
#define OFF_STAGE 0
#define OFF_FRAG  (2 * STAGE_BYTES)                  // 69632
#define OFF_B     (OFF_FRAG + 4 * FRAG_BYTES)        // 143360
#define B_BYTES   (4 * 16 * 32 * 16)                 // 32768
#define OFF_SBEST (OFF_B + B_BYTES)                  // 176128
#define SMEM_TOTAL (OFF_SBEST + 1024)                // 177152

__device__ unsigned long long g_best[QMAX];

__device__ __forceinline__ unsigned int fkey(float f) {
    unsigned int u = __float_as_uint(f);
    return (u & 0x80000000u) ? ~u : (u | 0x80000000u);
}
__device__ __forceinline__ uint32_t smem_u32(const void* p) {
    uint32_t a;
    asm("{ .reg .u64 t; cvta.to.shared.u64 t, %1; cvt.u32.u64 %0, t; }"
        : "=r"(a) : "l"(p));
    return a;
}
__device__ __forceinline__ void cpa16(uint32_t s, const void* g) {
    asm volatile("cp.async.cg.shared.global [%0], [%1], 16;" :: "r"(s), "l"(g));
}
// pack two f32 -> f16x2 (x0 low, x1 high); l = exact residual pair
__device__ __forceinline__ void split2h(float x0, float x1,
                                        uint32_t& h, uint32_t& l) {
    uint32_t hh;
    asm("cvt.rn.f16x2.f32 %0, %1, %2;" : "=r"(hh) : "f"(x1), "f"(x0));
    __half2 hv = *reinterpret_cast<__half2*>(&hh);
    float f0 = __low2float(hv), f1 = __high2float(hv);
    asm("cvt.rn.f16x2.f32 %0, %1, %2;" : "=r"(l) : "f"(x1 - f1), "f"(x0 - f0));
    h = hh;
}
#define MMA_F16(d, a0,a1,a2,a3, b0,b1) \
    asm volatile("mma.sync.aligned.m16n8k16.row.col.f32.f16.f16.f32 " \
        "{%0,%1,%2,%3}, {%4,%5,%6,%7}, {%8,%9}, {%0,%1,%2,%3};" \
        : "+f"((d)[0]), "+f"((d)[1]), "+f"((d)[2]), "+f"((d)[3]) \
        : "r"(a0), "r"(a1), "r"(a2), "r"(a3), "r"(b0), "r"(b1))

__global__ void init_best() {
    if (threadIdx.x < QMAX) g_best[threadIdx.x] = 0ull;
}

// producer staging: 128 threads x 16 chunks of 16B
__device__ __forceinline__ void stage_load_p(uint32_t dst, const float4* g4,
                                             long long tile, int N, int p)
{
#pragma unroll
    for (int i = 0; i < 16; ++i) {
        int j = p + i * 128;
        int row = j >> 4, k4 = j & 15;
        long long gr = tile * BM + row;
        if (gr >= N) gr = N - 1;
        cpa16(dst + (uint32_t)(row * RSTRIDE + k4 * 4) * 4u,
              g4 + gr * (KD / 4) + k4);
    }
    asm volatile("cp.async.commit_group;" ::: "memory");
}

// producer convert: row p fp32 -> inv-norm-scaled fp16 hi/lo frags
__device__ __forceinline__ void convert_row(const float* stg, char* smem,
                                            uint32_t fb, int p)
{
    const float4* rp = (const float4*)(stg + p * RSTRIDE);
    float ss = 0.f;
#pragma unroll
    for (int i = 0; i < 16; ++i) {
        float4 x = rp[i];
        ss = fmaf(x.x, x.x, ss);
        ss = fmaf(x.y, x.y, ss);
        ss = fmaf(x.z, x.z, ss);
        ss = fmaf(x.w, x.w, ss);
    }
    float inv = (ss > 1e-30f) ? rsqrtf(ss) : 0.f;
    uint32_t* hp = (uint32_t*)(smem + fb) + p * ARS;
    uint32_t* lp = (uint32_t*)(smem + fb + FRAG_BYTES) + p * ARS;
#pragma unroll
    for (int j = 0; j < 8; ++j) {
        float4 a = rp[2 * j];
        float4 b = rp[2 * j + 1];
        uint4 hv, lv;
        split2h(a.x * inv, a.y * inv, hv.x, lv.x);
        split2h(a.z * inv, a.w * inv, hv.y, lv.y);
        split2h(b.x * inv, b.y * inv, hv.z, lv.z);
        split2h(b.z * inv, b.w * inv, hv.w, lv.w);
        *(uint4*)&hp[j * 4] = hv;
        *(uint4*)&lp[j * 4] = lv;
    }
}

extern "C" __global__ void __launch_bounds__(TPB, 1)
sim_argmax(const float* __restrict__ actions, const float* __restrict__ pred,
           int N, int Q)
{
    extern __shared__ char smem[];
    const uint32_t sb = smem_u32(smem);
    float* stage = (float*)smem;
    unsigned long long* sbest = (unsigned long long*)(smem + OFF_SBEST);

    const int tid  = threadIdx.x;
    const int lane = tid & 31;
    const int w    = tid >> 5;
    const bool producer = (tid >= 128);
    const int p = tid & 127;

    // ---- B fragments once (all 256 threads): [ks][nt][lane] uint4
    //      {bh(k0,k1), bh(k+8), bl(k0,k1), bl(k+8)}
#pragma unroll
    for (int i = 0; i < 8; ++i) {
        int slot = tid + i * TPB;
        int ks = slot >> 9;
        int nt = (slot >> 5) & 15;
        int l  = slot & 31;
        int q  = nt * 8 + (l >> 2);
        int k0 = ks * 16 + (l & 3) * 2;
        float x0 = 0.f, x1 = 0.f, x2 = 0.f, x3 = 0.f;
        if (q < Q) {
            x0 = pred[q * KD + k0];
            x1 = pred[q * KD + k0 + 1];
            x2 = pred[q * KD + k0 + 8];
            x3 = pred[q * KD + k0 + 9];
        }
        uint4 v;
        split2h(x0, x1, v.x, v.z);
        split2h(x2, x3, v.y, v.w);
        *(uint4*)(smem + OFF_B + slot * 16) = v;
    }
    if (tid < QMAX) sbest[tid] = 0ull;

    const long long ntiles = ((long long)N + BM - 1) / BM;
    const long long G = gridDim.x;
    const long long t0 = blockIdx.x;
    const float4* g4 = (const float4*)actions;

    // consumer argmax state: 32 query slots
    float        bs[32];
    unsigned int br[32];
#pragma unroll
    for (int j = 0; j < 32; ++j) { bs[j] = -3.4e38f; br[j] = 0u; }

    // ---- prologue: stage(t0)->buf0, convert frags0, stage(t0+G)->buf1
    if (producer) {
        if (t0 < ntiles) {
            stage_load_p(sb + OFF_STAGE, g4, t0, N, p);
            asm volatile("cp.async.wait_group 0;" ::: "memory");
            asm volatile("bar.sync 1, 128;" ::: "memory");
            convert_row(stage, smem, OFF_FRAG, p);
            if (t0 + G < ntiles)
                stage_load_p(sb + OFF_STAGE + STAGE_BYTES, g4, t0 + G, N, p);
        }
    }
    __syncthreads();

    long long tile = t0;
    int it = 0;
    for (; tile < ntiles; tile += G, ++it) {
        if (!producer) {
            // ---- consumer: MMA frags[it&1] + argmax epilogue
            const uint32_t fb = OFF_FRAG + (uint32_t)(it & 1) * (2 * FRAG_BYTES);
            const uint32_t* ah = (const uint32_t*)(smem + fb);
            const uint32_t* al = (const uint32_t*)(smem + fb + FRAG_BYTES);
            const int rw = lane >> 2, c4 = lane & 3;

#pragma unroll
            for (int hf = 0; hf < 2; ++hf) {
                float d[2][8][4];
#pragma unroll
                for (int mt = 0; mt < 2; ++mt)
#pragma unroll
                    for (int n = 0; n < 8; ++n)
#pragma unroll
                        for (int c = 0; c < 4; ++c) d[mt][n][c] = 0.f;

#pragma unroll
                for (int ks = 0; ks < 4; ++ks) {
                    uint32_t A0[2], A1[2], A2[2], A3[2];
                    uint32_t E0[2], E1[2], E2[2], E3[2];
#pragma unroll
                    for (int mt = 0; mt < 2; ++mt) {
                        int R  = w * 32 + mt * 16 + rw;
                        int b0 = R * ARS + ks * 8 + c4;
                        int b8 = (R + 8) * ARS + ks * 8 + c4;
                        A0[mt] = ah[b0];     A1[mt] = ah[b8];
                        A2[mt] = ah[b0 + 4]; A3[mt] = ah[b8 + 4];
                        E0[mt] = al[b0];     E1[mt] = al[b8];
                        E2[mt] = al[b0 + 4]; E3[mt] = al[b8 + 4];
                    }
#pragma unroll
                    for (int n = 0; n < 8; ++n) {
                        uint4 b = *(const uint4*)(smem + OFF_B +
                                  (((ks * 16 + hf * 8 + n) * 32 + lane) << 4));
#pragma unroll
                        for (int mt = 0; mt < 2; ++mt) {
                            MMA_F16(d[mt][n], A0[mt],A1[mt],A2[mt],A3[mt], b.x, b.y);
                            MMA_F16(d[mt][n], A0[mt],A1[mt],A2[mt],A3[mt], b.z, b.w);
                            MMA_F16(d[mt][n], E0[mt],E1[mt],E2[mt],E3[mt], b.x, b.y);
                        }
                    }
                }
                // epilogue (scores already normalized)
#pragma unroll
                for (int mt = 0; mt < 2; ++mt) {
                    long long gr0 = tile * BM + w * 32 + mt * 16 + rw;
                    bool ok0 = (gr0 < N);
                    bool ok1 = (gr0 + 8 < N);
#pragma unroll
                    for (int n = 0; n < 8; ++n) {
                        int j = (hf * 8 + n) * 2;
                        float* dd = d[mt][n];
                        if (ok0) {
                            if (dd[0] > bs[j])     { bs[j] = dd[0];     br[j] = (unsigned)gr0; }
                            if (dd[1] > bs[j + 1]) { bs[j + 1] = dd[1]; br[j + 1] = (unsigned)gr0; }
                        }
                        if (ok1) {
                            if (dd[2] > bs[j])     { bs[j] = dd[2];     br[j] = (unsigned)(gr0 + 8); }
                            if (dd[3] > bs[j + 1]) { bs[j + 1] = dd[3]; br[j + 1] = (unsigned)(gr0 + 8); }
                        }
                    }
                }
            }
        } else {
            // ---- producer: convert tile(it+1), then stage tile(it+2)
            long long tc = tile + G;
            if (tc < ntiles) {
                asm volatile("cp.async.wait_group 0;" ::: "memory");
                asm volatile("bar.sync 1, 128;" ::: "memory");
                convert_row(stage + ((it + 1) & 1) * (BM * RSTRIDE), smem,
                            OFF_FRAG + (uint32_t)((it + 1) & 1) * (2 * FRAG_BYTES),
                            p);
            }
            long long tl = tile + 2 * G;
            if (tl < ntiles)
                stage_load_p(sb + OFF_STAGE + (uint32_t)(it & 1) * STAGE_BYTES,
                             g4, tl, N, p);
        }
        __syncthreads();
    }

    // ---- merge: consumer lanes sharing a query shuffle-reduce, then atomics
    if (!producer) {
#pragma unroll
        for (int j = 0; j < 32; ++j) {
            unsigned long long pk = 0ull;
            if (bs[j] > -1e37f)
                pk = ((unsigned long long)fkey(bs[j]) << 32) |
                     (unsigned long long)(~br[j]);
#pragma unroll
            for (int off = 4; off <= 16; off <<= 1) {
                unsigned long long o = __shfl_xor_sync(0xffffffffu, pk, off);
                if (o > pk) pk = o;
            }
            if ((lane & 28) == 0 && pk) {
                int nt = j >> 1;
                int q = nt * 8 + (lane & 3) * 2 + (j & 1);
                atomicMax(&sbest[q], pk);
            }
        }
    }
    __syncthreads();
    if (tid < QMAX) {
        unsigned long long v = sbest[tid];
        if (v) atomicMax(&g_best[tid], v);
    }
}

__global__ void gather(const float* __restrict__ actions,
                       float* __restrict__ out, int Q) {
    int q = blockIdx.x;
    int t = threadIdx.x;
    if (q < Q) {
        unsigned int idx = ~(unsigned int)(g_best[q] & 0xFFFFFFFFull);
        out[(size_t)q * KD + t] = actions[(size_t)idx * KD + t];
    }
}

extern "C" void kernel_launch(void* const* d_in, const int* in_sizes, int n_in,
                              void* d_out, int out_size) {
    int ip = 0, ia = 1;
    if (n_in >= 2 && in_sizes[0] > in_sizes[1]) { ip = 1; ia = 0; }
    const float* pred    = (const float*)d_in[ip];
    const float* actions = (const float*)d_in[ia];
    int Q = in_sizes[ip] / KD;
    if (Q > QMAX) Q = QMAX;
    int N = in_sizes[ia] / KD;

    cudaFuncSetAttribute(sim_argmax,
                         cudaFuncAttributeMaxDynamicSharedMemorySize,
                         SMEM_TOTAL);

    init_best<<<1, 128>>>();
    sim_argmax<<<148, TPB, SMEM_TOTAL>>>(actions, pred, N, Q);
    gather<<<Q, KD>>>(actions, (float*)d_out, Q);
}